// round 4
// baseline (speedup 1.0000x reference)
#include <cuda_runtime.h>
#include <cuda_bf16.h>
#include <mma.h>
#include <cstdint>

using namespace nvcuda;

// Problem constants
#define BB   4
#define SS   2048
#define DIMM 2048
#define HH   16
#define HDD  128
#define MM   (BB*SS)            // 8192
#define SCALE 0.08838834764831845f   // 1/sqrt(128)
#define BIGNEG (-1e30f)

// ---------------- scratch (__device__ globals: allocation-free) -------------
// Referenced directly from device code; NO cudaGetSymbolAddress on host.
__device__ float g_qt [MM*DIMM];   // Q normed+roped, (B,H,S,HD)
__device__ float g_kt [MM*DIMM];   // K normed+roped, (B,H,S,HD)
__device__ float g_v  [MM*DIMM];   // V projection,   (B,S,DIM)
__device__ float g_at [MM*DIMM];   // attention out,  (B,S,DIM)

__device__ __forceinline__ float to_tf32(float x) {
    uint32_t u;
    asm("cvt.rna.tf32.f32 %0, %1;" : "=r"(u) : "f"(x));
    return __uint_as_float(u);
}

// =============================== GEMM core ==================================
// C[M,N] = A[M,K] @ W[N,K]^T   (M=8192, N=K=2048), TF32 via wmma m16n16k8.
// Block tile 128x128x32, 256 threads (8 warps, 4x2), warp tile 32x64.
#define G_BM 128
#define G_BN 128
#define G_BK 32
#define G_LD 36   // padded smem ld

#define GEMM_MAINLOOP(As, Bs)                                                  \
    wmma::fragment<wmma::accumulator, 16, 16, 8, float> acc[2][4];             \
    _Pragma("unroll")                                                          \
    for (int i = 0; i < 2; i++)                                                \
        _Pragma("unroll")                                                      \
        for (int j = 0; j < 4; j++) wmma::fill_fragment(acc[i][j], 0.0f);      \
    for (int k0 = 0; k0 < DIMM; k0 += G_BK) {                                  \
        _Pragma("unroll")                                                      \
        for (int p = 0; p < 4; p++) {                                          \
            int idx = tid + p * 256;                                           \
            int r  = idx >> 3;                                                 \
            int c4 = (idx & 7) << 2;                                           \
            float4 va = *(const float4*)&A[(bm + r) * DIMM + k0 + c4];         \
            float4 vb = *(const float4*)&W[(bn + r) * DIMM + k0 + c4];         \
            va.x = to_tf32(va.x); va.y = to_tf32(va.y);                        \
            va.z = to_tf32(va.z); va.w = to_tf32(va.w);                        \
            vb.x = to_tf32(vb.x); vb.y = to_tf32(vb.y);                        \
            vb.z = to_tf32(vb.z); vb.w = to_tf32(vb.w);                        \
            *(float4*)&(As)[r * G_LD + c4] = va;                               \
            *(float4*)&(Bs)[r * G_LD + c4] = vb;                               \
        }                                                                      \
        __syncthreads();                                                       \
        _Pragma("unroll")                                                      \
        for (int kk = 0; kk < G_BK; kk += 8) {                                 \
            wmma::fragment<wmma::matrix_a, 16, 16, 8, wmma::precision::tf32,   \
                           wmma::row_major> af[2];                             \
            wmma::fragment<wmma::matrix_b, 16, 16, 8, wmma::precision::tf32,   \
                           wmma::col_major> bf[4];                             \
            _Pragma("unroll")                                                  \
            for (int i = 0; i < 2; i++)                                        \
                wmma::load_matrix_sync(af[i],                                  \
                    &(As)[(wm * 32 + i * 16) * G_LD + kk], G_LD);              \
            _Pragma("unroll")                                                  \
            for (int j = 0; j < 4; j++)                                        \
                wmma::load_matrix_sync(bf[j],                                  \
                    &(Bs)[(wn * 64 + j * 16) * G_LD + kk], G_LD);              \
            _Pragma("unroll")                                                  \
            for (int i = 0; i < 2; i++)                                        \
                _Pragma("unroll")                                              \
                for (int j = 0; j < 4; j++)                                    \
                    wmma::mma_sync(acc[i][j], af[i], bf[j], acc[i][j]);        \
        }                                                                      \
        __syncthreads();                                                       \
    }

// ---- plain GEMM: X @ Wv^T -> g_v (B,S,DIM) ----
__global__ __launch_bounds__(256) void gemm_v(const float* __restrict__ A,
                                              const float* __restrict__ W) {
    __shared__ float As[G_BM * G_LD];
    __shared__ float Bs[G_BN * G_LD];
    const int bm = blockIdx.y * G_BM;
    const int bn = blockIdx.x * G_BN;
    const int tid = threadIdx.x;
    const int warp = tid >> 5;
    const int wm = warp >> 1;
    const int wn = warp & 1;
    GEMM_MAINLOOP(As, Bs)
#pragma unroll
    for (int i = 0; i < 2; i++)
#pragma unroll
        for (int j = 0; j < 4; j++)
            wmma::store_matrix_sync(
                &g_v[(bm + wm * 32 + i * 16) * DIMM + bn + wn * 64 + j * 16],
                acc[i][j], DIMM, wmma::mem_row_major);
}

// ---- plain GEMM: g_at @ Wo^T -> out ----
__global__ __launch_bounds__(256) void gemm_out(const float* __restrict__ W,
                                                float* __restrict__ C) {
    __shared__ float As[G_BM * G_LD];
    __shared__ float Bs[G_BN * G_LD];
    const float* A = g_at;
    const int bm = blockIdx.y * G_BM;
    const int bn = blockIdx.x * G_BN;
    const int tid = threadIdx.x;
    const int warp = tid >> 5;
    const int wm = warp >> 1;
    const int wn = warp & 1;
    GEMM_MAINLOOP(As, Bs)
#pragma unroll
    for (int i = 0; i < 2; i++)
#pragma unroll
        for (int j = 0; j < 4; j++)
            wmma::store_matrix_sync(
                &C[(bm + wm * 32 + i * 16) * DIMM + bn + wn * 64 + j * 16],
                acc[i][j], DIMM, wmma::mem_row_major);
}

// ---- fused GEMM + RMSNorm + RoPE + transpose for Q/K ----
// Each 128-wide column tile == exactly one head (HD=128), so the full head row
// needed by the RMS reduction is inside this block's C tile.
// Output: ((b*H + h)*S + s)*HD  in g_qt (which=0) or g_kt (which=1).
#define C_LD 132
#define QK_SMEM (G_BM * C_LD * 4)   // 67584 bytes (> As+Bs = 36864)

__global__ __launch_bounds__(256) void gemm_qk(const float* __restrict__ A,
                                               const float* __restrict__ W,
                                               const float* __restrict__ nw,
                                               const float* __restrict__ ct,
                                               const float* __restrict__ st,
                                               int which) {
    extern __shared__ float dsm[];
    float* As = dsm;
    float* Bs = dsm + G_BM * G_LD;
    const int bm = blockIdx.y * G_BM;
    const int bn = blockIdx.x * G_BN;
    const int tid = threadIdx.x;
    const int warp = tid >> 5;
    const int wm = warp >> 1;
    const int wn = warp & 1;
    GEMM_MAINLOOP(As, Bs)

    // Mainloop ends with __syncthreads(): safe to overwrite As/Bs with C tile.
    float* Cs = dsm;
#pragma unroll
    for (int i = 0; i < 2; i++)
#pragma unroll
        for (int j = 0; j < 4; j++)
            wmma::store_matrix_sync(&Cs[(wm * 32 + i * 16) * C_LD + wn * 64 + j * 16],
                                    acc[i][j], C_LD, wmma::mem_row_major);
    __syncthreads();

    // Epilogue: one warp per row, 16 rows per warp. lane holds dims 4l..4l+3.
    const int lane = tid & 31;
    const int h = bn >> 7;
    const float4 wv4 = ((const float4*)nw)[lane];
    const float sgn = (lane < 16) ? -1.0f : 1.0f;
    float* dstT = which ? g_kt : g_qt;

#pragma unroll
    for (int i = 0; i < 16; i++) {
        const int r = warp + 8 * i;            // 0..127
        float4 v = *(const float4*)&Cs[r * C_LD + lane * 4];
        float ssum = v.x * v.x + v.y * v.y + v.z * v.z + v.w * v.w;
#pragma unroll
        for (int o = 16; o; o >>= 1) ssum += __shfl_xor_sync(0xffffffffu, ssum, o);
        const float rinv = rsqrtf(ssum * (1.0f / HDD) + 1e-6f);

        float n0 = v.x * rinv * wv4.x;
        float n1 = v.y * rinv * wv4.y;
        float n2 = v.z * rinv * wv4.z;
        float n3 = v.w * rinv * wv4.w;

        // rotate-half partner: dim d ^ 64 == lane ^ 16, same vector slot
        float o0 = __shfl_xor_sync(0xffffffffu, n0, 16);
        float o1 = __shfl_xor_sync(0xffffffffu, n1, 16);
        float o2 = __shfl_xor_sync(0xffffffffu, n2, 16);
        float o3 = __shfl_xor_sync(0xffffffffu, n3, 16);

        const int m = bm + r;
        const int b = m >> 11;                 // m / S
        const int s = m & (SS - 1);            // m % S

        const float4 c4 = ((const float4*)(ct + s * HDD))[lane];
        const float4 s4 = ((const float4*)(st + s * HDD))[lane];
        float4 outv;
        outv.x = n0 * c4.x + sgn * o0 * s4.x;
        outv.y = n1 * c4.y + sgn * o1 * s4.y;
        outv.z = n2 * c4.z + sgn * o2 * s4.z;
        outv.w = n3 * c4.w + sgn * o3 * s4.w;

        ((float4*)&dstT[((b * HH + h) * SS + s) * HDD])[lane] = outv;
    }
}

// ============================ Flash attention ===============================
// TF32 mma.sync.m16n8k8; block = (b,h) x 128 query rows, 8 warps (16 rows each),
// KV tiles of 64. Online softmax in registers (known C-fragment layout).
#define F_QT 128
#define F_KT 64
#define F_LQ 132                       // q/k smem ld (floats)
#define F_LV 68                        // v^T smem ld
#define F_LP 68                        // per-warp P ld
#define F_OFF_K (F_QT * F_LQ)          // 16896
#define F_OFF_V (F_OFF_K + F_KT * F_LQ)        // 25344
#define F_OFF_P (F_OFF_V + HDD * F_LV)         // 34048
#define F_SM_FLOATS (F_OFF_P + 8 * 16 * F_LP)  // 42752 -> 171008 B

#define MMA_TF32(Cr, a0, a1, a2, a3, b0, b1)                                  \
    asm volatile("mma.sync.aligned.m16n8k8.row.col.f32.tf32.tf32.f32 "        \
                 "{%0,%1,%2,%3}, {%4,%5,%6,%7}, {%8,%9}, {%0,%1,%2,%3};"      \
                 : "+f"(Cr[0]), "+f"(Cr[1]), "+f"(Cr[2]), "+f"(Cr[3])         \
                 : "r"(a0), "r"(a1), "r"(a2), "r"(a3), "r"(b0), "r"(b1))

__global__ __launch_bounds__(256, 1) void flash_attn() {
    extern __shared__ float sm[];
    float* qs = sm;
    float* ks = sm + F_OFF_K;
    float* vt = sm + F_OFF_V;

    const float* qT = g_qt;
    const float* kT = g_kt;
    const float* vI = g_v;
    float* outA = g_at;

    const int tid = threadIdx.x;
    const int w = tid >> 5;
    const int lane = tid & 31;
    const int g = lane >> 2;     // groupID 0..7
    const int q = lane & 3;      // thread-in-group 0..3
    const int bh = blockIdx.y;
    const int b = bh >> 4, h = bh & 15;
    const int qt0 = blockIdx.x * F_QT;
    float* pw = sm + F_OFF_P + w * 16 * F_LP;

    // ---- load Q tile (128 x 128) into smem, tf32-rounded ----
    const float* qbase = qT + (bh * SS + qt0) * HDD;
#pragma unroll
    for (int p = 0; p < 16; p++) {
        int idx = tid + p * 256;        // 0..4095
        int r = idx >> 5, c4 = (idx & 31) << 2;
        float4 vq = *(const float4*)&qbase[r * HDD + c4];
        vq.x = to_tf32(vq.x); vq.y = to_tf32(vq.y);
        vq.z = to_tf32(vq.z); vq.w = to_tf32(vq.w);
        *(float4*)&qs[r * F_LQ + c4] = vq;
    }

    float o[16][4];
#pragma unroll
    for (int nt = 0; nt < 16; nt++)
#pragma unroll
        for (int e = 0; e < 4; e++) o[nt][e] = 0.0f;
    float m0 = BIGNEG, m1 = BIGNEG, l0 = 0.0f, l1 = 0.0f;

    const int row0g = qt0 + w * 16 + g;
    const int row1g = row0g + 8;
    const int nj = 2 * blockIdx.x + 2;   // causal: kv tiles needed

    for (int j = 0; j < nj; j++) {
        // ---- load K tile (64 x 128) ----
        const float* kbase = kT + (bh * SS + j * F_KT) * HDD;
#pragma unroll
        for (int p = 0; p < 8; p++) {
            int idx = tid + p * 256;
            int r = idx >> 5, c4 = (idx & 31) << 2;
            float4 vk = *(const float4*)&kbase[r * HDD + c4];
            vk.x = to_tf32(vk.x); vk.y = to_tf32(vk.y);
            vk.z = to_tf32(vk.z); vk.w = to_tf32(vk.w);
            *(float4*)&ks[r * F_LQ + c4] = vk;
        }
        // ---- load V tile transposed: vt[d][kv] ----
        const float* vbase = vI + (b * SS + j * F_KT) * DIMM + h * HDD;
#pragma unroll
        for (int p = 0; p < 8; p++) {
            int idx = tid + p * 256;
            int r = idx >> 5, c4 = (idx & 31) << 2;
            float4 vv = *(const float4*)&vbase[r * DIMM + c4];
            vt[(c4 + 0) * F_LV + r] = to_tf32(vv.x);
            vt[(c4 + 1) * F_LV + r] = to_tf32(vv.y);
            vt[(c4 + 2) * F_LV + r] = to_tf32(vv.z);
            vt[(c4 + 3) * F_LV + r] = to_tf32(vv.w);
        }
        __syncthreads();

        // ---- S = Q @ K^T : 16 x 64 per warp ----
        float c[8][4];
#pragma unroll
        for (int nt = 0; nt < 8; nt++)
#pragma unroll
            for (int e = 0; e < 4; e++) c[nt][e] = 0.0f;
#pragma unroll
        for (int ks8 = 0; ks8 < 16; ks8++) {
            const int kk = ks8 * 8;
            uint32_t a0 = __float_as_uint(qs[(w * 16 + g)     * F_LQ + kk + q]);
            uint32_t a1 = __float_as_uint(qs[(w * 16 + g + 8) * F_LQ + kk + q]);
            uint32_t a2 = __float_as_uint(qs[(w * 16 + g)     * F_LQ + kk + q + 4]);
            uint32_t a3 = __float_as_uint(qs[(w * 16 + g + 8) * F_LQ + kk + q + 4]);
#pragma unroll
            for (int nt = 0; nt < 8; nt++) {
                uint32_t b0 = __float_as_uint(ks[(nt * 8 + g) * F_LQ + kk + q]);
                uint32_t b1 = __float_as_uint(ks[(nt * 8 + g) * F_LQ + kk + q + 4]);
                MMA_TF32(c[nt], a0, a1, a2, a3, b0, b1);
            }
        }

        // ---- online softmax (rows r0=g, r1=g+8 of this warp) ----
        float mx0 = BIGNEG, mx1 = BIGNEG;
#pragma unroll
        for (int nt = 0; nt < 8; nt++) {
            const int cb = j * F_KT + nt * 8 + q * 2;
            c[nt][0] = (cb     <= row0g) ? c[nt][0] * SCALE : BIGNEG;
            c[nt][1] = (cb + 1 <= row0g) ? c[nt][1] * SCALE : BIGNEG;
            c[nt][2] = (cb     <= row1g) ? c[nt][2] * SCALE : BIGNEG;
            c[nt][3] = (cb + 1 <= row1g) ? c[nt][3] * SCALE : BIGNEG;
            mx0 = fmaxf(mx0, fmaxf(c[nt][0], c[nt][1]));
            mx1 = fmaxf(mx1, fmaxf(c[nt][2], c[nt][3]));
        }
        mx0 = fmaxf(mx0, __shfl_xor_sync(0xffffffffu, mx0, 1));
        mx0 = fmaxf(mx0, __shfl_xor_sync(0xffffffffu, mx0, 2));
        mx1 = fmaxf(mx1, __shfl_xor_sync(0xffffffffu, mx1, 1));
        mx1 = fmaxf(mx1, __shfl_xor_sync(0xffffffffu, mx1, 2));

        const float mn0 = fmaxf(m0, mx0), mn1 = fmaxf(m1, mx1);
        const float al0 = __expf(m0 - mn0), al1 = __expf(m1 - mn1);
        float sum0 = 0.0f, sum1 = 0.0f;
#pragma unroll
        for (int nt = 0; nt < 8; nt++) {
            c[nt][0] = __expf(c[nt][0] - mn0); sum0 += c[nt][0];
            c[nt][1] = __expf(c[nt][1] - mn0); sum0 += c[nt][1];
            c[nt][2] = __expf(c[nt][2] - mn1); sum1 += c[nt][2];
            c[nt][3] = __expf(c[nt][3] - mn1); sum1 += c[nt][3];
        }
        sum0 += __shfl_xor_sync(0xffffffffu, sum0, 1);
        sum0 += __shfl_xor_sync(0xffffffffu, sum0, 2);
        sum1 += __shfl_xor_sync(0xffffffffu, sum1, 1);
        sum1 += __shfl_xor_sync(0xffffffffu, sum1, 2);
        l0 = l0 * al0 + sum0;
        l1 = l1 * al1 + sum1;
        m0 = mn0; m1 = mn1;
#pragma unroll
        for (int nt = 0; nt < 16; nt++) {
            o[nt][0] *= al0; o[nt][1] *= al0;
            o[nt][2] *= al1; o[nt][3] *= al1;
        }

        // ---- write P (16x64) to per-warp smem, tf32-rounded ----
#pragma unroll
        for (int nt = 0; nt < 8; nt++) {
            pw[g       * F_LP + nt * 8 + q * 2 + 0] = to_tf32(c[nt][0]);
            pw[g       * F_LP + nt * 8 + q * 2 + 1] = to_tf32(c[nt][1]);
            pw[(g + 8) * F_LP + nt * 8 + q * 2 + 0] = to_tf32(c[nt][2]);
            pw[(g + 8) * F_LP + nt * 8 + q * 2 + 1] = to_tf32(c[nt][3]);
        }
        __syncwarp();

        // ---- O += P @ V : 16 x 128 per warp ----
#pragma unroll
        for (int ks8 = 0; ks8 < 8; ks8++) {
            const int kk = ks8 * 8;
            uint32_t a0 = __float_as_uint(pw[g       * F_LP + kk + q]);
            uint32_t a1 = __float_as_uint(pw[(g + 8) * F_LP + kk + q]);
            uint32_t a2 = __float_as_uint(pw[g       * F_LP + kk + q + 4]);
            uint32_t a3 = __float_as_uint(pw[(g + 8) * F_LP + kk + q + 4]);
#pragma unroll
            for (int nt = 0; nt < 16; nt++) {
                uint32_t b0 = __float_as_uint(vt[(nt * 8 + g) * F_LV + kk + q]);
                uint32_t b1 = __float_as_uint(vt[(nt * 8 + g) * F_LV + kk + q + 4]);
                MMA_TF32(o[nt], a0, a1, a2, a3, b0, b1);
            }
        }
        __syncthreads();
    }

    // ---- epilogue: O / l -> (B,S,DIM) layout for the output GEMM ----
    const float inv0 = 1.0f / l0, inv1 = 1.0f / l1;
    float* ob0 = outA + (b * SS + row0g) * DIMM + h * HDD;
    float* ob1 = outA + (b * SS + row1g) * DIMM + h * HDD;
#pragma unroll
    for (int nt = 0; nt < 16; nt++) {
        const int d = nt * 8 + q * 2;
        *(float2*)&ob0[d] = make_float2(o[nt][0] * inv0, o[nt][1] * inv0);
        *(float2*)&ob1[d] = make_float2(o[nt][2] * inv1, o[nt][3] * inv1);
    }
}

// =============================== launch =====================================
extern "C" void kernel_launch(void* const* d_in, const int* in_sizes, int n_in,
                              void* d_out, int out_size) {
    (void)in_sizes; (void)n_in; (void)out_size;
    const float* x  = (const float*)d_in[0];
    const float* ct = (const float*)d_in[1];
    const float* st = (const float*)d_in[2];
    // d_in[3] = causal mask (tril) — implemented analytically
    const float* wq = (const float*)d_in[4];
    const float* wk = (const float*)d_in[5];
    const float* wv = (const float*)d_in[6];
    const float* wo = (const float*)d_in[7];
    const float* qw = (const float*)d_in[8];
    const float* kw = (const float*)d_in[9];
    float* out = (float*)d_out;

    cudaFuncSetAttribute(gemm_qk, cudaFuncAttributeMaxDynamicSharedMemorySize,
                         QK_SMEM);
    cudaFuncSetAttribute(flash_attn, cudaFuncAttributeMaxDynamicSharedMemorySize,
                         F_SM_FLOATS * (int)sizeof(float));

    const dim3 gGrid(DIMM / G_BN, MM / G_BM);   // (16, 64)

    gemm_qk<<<gGrid, 256, QK_SMEM>>>(x, wq, qw, ct, st, 0);
    gemm_qk<<<gGrid, 256, QK_SMEM>>>(x, wk, kw, ct, st, 1);
    gemm_v <<<gGrid, 256>>>(x, wv);

    flash_attn<<<dim3(SS / F_QT, BB * HH), 256, F_SM_FLOATS * sizeof(float)>>>();

    gemm_out<<<gGrid, 256>>>(wo, out);
}